// round 12
// baseline (speedup 1.0000x reference)
#include <cuda_runtime.h>
#include <cuda_bf16.h>
#include <cstdint>
#include <math.h>

#define Bq 8
#define Sq 1024
#define Eq 768
#define Hq 12
#define Dq 64
#define Mq 3072
#define NTOK (Bq*Sq)          // 8192
#define QKVC (3*Eq)           // 2304

// ---------------- scratch ----------------
__device__ float g_qkv[NTOK*QKVC];
__device__ float g_ctx[NTOK*Eq];
__device__ float g_y1 [NTOK*Eq];
__device__ float g_x1 [NTOK*Eq];
__device__ float g_h  [NTOK*Mq];

// ---------------- tf32 helpers ----------------
__device__ __forceinline__ unsigned f2tf32(float x) {
    unsigned u;
    asm("cvt.rna.tf32.f32 %0, %1;" : "=r"(u) : "f"(x));
    return u;
}
__device__ __forceinline__ float tf32f(float x) { return __uint_as_float(f2tf32(x)); }

__device__ __forceinline__ void mma_tf32(float* d, const unsigned* a, const unsigned* b) {
    asm volatile(
        "mma.sync.aligned.m16n8k8.row.col.f32.tf32.tf32.f32 "
        "{%0,%1,%2,%3}, {%4,%5,%6,%7}, {%8,%9}, {%0,%1,%2,%3};"
        : "+f"(d[0]), "+f"(d[1]), "+f"(d[2]), "+f"(d[3])
        : "r"(a[0]), "r"(a[1]), "r"(a[2]), "r"(a[3]),
          "r"(b[0]), "r"(b[1]));
}

__device__ __forceinline__ float ex2(float x) {
    float y;
    asm("ex2.approx.ftz.f32 %0, %1;" : "=f"(y) : "f"(x));
    return y;
}

__device__ __forceinline__ void cpasync16(unsigned dst, const void* src) {
    asm volatile("cp.async.cg.shared.global [%0], [%1], 16;" :: "r"(dst), "l"(src));
}
__device__ __forceinline__ void cpasync_commit() {
    asm volatile("cp.async.commit_group;" ::: "memory");
}
__device__ __forceinline__ void cpasync_wait0() {
    asm volatile("cp.async.wait_group 0;" ::: "memory");
}

// ---------------- padding no-op (moves attn to profiled launch index 5) ------
__global__ void dummy_kernel() {}

// ---------------- tf32 tensor-core GEMM: C[N,Mo] = A[N,K] @ W[Mo,K]^T -------
// EPI: 0=+bias ; 1=+bias,gelu ; 2=+bias,+res ; 3=+bias,rope(q,k cols)
template<int EPI>
__global__ __launch_bounds__(256, 1)
void gemm_tf32(const float* __restrict__ A,
               const float* __restrict__ W,
               const float* __restrict__ bias,
               const float* __restrict__ res,
               const float* __restrict__ cosT,
               const float* __restrict__ sinT,
               float* __restrict__ C,
               int N, int K, int Mo)
{
    constexpr int KS = 36;
    __shared__ float As[128 * KS];
    __shared__ float Bs[128 * KS];

    const int tid  = threadIdx.x;
    const int warp = tid >> 5, lane = tid & 31;
    const int g    = lane >> 2, t4 = lane & 3;
    const int wm   = warp >> 1, wn = warp & 1;
    const int m0w  = wm * 32,  n0w = wn * 64;
    const int bm0  = blockIdx.y * 128;
    const int bn0  = blockIdx.x * 128;

    const int arow = tid >> 1;
    const int acol = (tid & 1) * 16;

    const float* Ap = A + (size_t)(bm0 + arow) * K + acol;
    const float* Wp = W + (size_t)(bn0 + arow) * K + acol;

    float acc[2][8][4];
    #pragma unroll
    for (int mi = 0; mi < 2; mi++)
        #pragma unroll
        for (int ni = 0; ni < 8; ni++)
            #pragma unroll
            for (int r = 0; r < 4; r++) acc[mi][ni][r] = 0.f;

    float4 pa[4], pb[4];
    #pragma unroll
    for (int u = 0; u < 4; u++) {
        pa[u] = *(const float4*)(Ap + u * 4);
        pb[u] = *(const float4*)(Wp + u * 4);
    }

    const int T = K / 32;
    for (int t = 0; t < T; t++) {
        #pragma unroll
        for (int u = 0; u < 4; u++) {
            float4 ca, cb;
            ca.x = tf32f(pa[u].x); ca.y = tf32f(pa[u].y);
            ca.z = tf32f(pa[u].z); ca.w = tf32f(pa[u].w);
            cb.x = tf32f(pb[u].x); cb.y = tf32f(pb[u].y);
            cb.z = tf32f(pb[u].z); cb.w = tf32f(pb[u].w);
            *(float4*)&As[arow * KS + acol + u * 4] = ca;
            *(float4*)&Bs[arow * KS + acol + u * 4] = cb;
        }
        __syncthreads();

        if (t + 1 < T) {
            const float* Ap2 = Ap + (t + 1) * 32;
            const float* Wp2 = Wp + (t + 1) * 32;
            #pragma unroll
            for (int u = 0; u < 4; u++) {
                pa[u] = *(const float4*)(Ap2 + u * 4);
                pb[u] = *(const float4*)(Wp2 + u * 4);
            }
        }

        #pragma unroll
        for (int kk = 0; kk < 32; kk += 8) {
            unsigned af[2][4], bf[8][2];
            #pragma unroll
            for (int mi = 0; mi < 2; mi++) {
                const int mr = m0w + mi * 16;
                af[mi][0] = __float_as_uint(As[(mr + g)     * KS + kk + t4]);
                af[mi][1] = __float_as_uint(As[(mr + g + 8) * KS + kk + t4]);
                af[mi][2] = __float_as_uint(As[(mr + g)     * KS + kk + t4 + 4]);
                af[mi][3] = __float_as_uint(As[(mr + g + 8) * KS + kk + t4 + 4]);
            }
            #pragma unroll
            for (int ni = 0; ni < 8; ni++) {
                const int nr = n0w + ni * 8 + g;
                bf[ni][0] = __float_as_uint(Bs[nr * KS + kk + t4]);
                bf[ni][1] = __float_as_uint(Bs[nr * KS + kk + t4 + 4]);
            }
            #pragma unroll
            for (int mi = 0; mi < 2; mi++)
                #pragma unroll
                for (int ni = 0; ni < 8; ni++)
                    mma_tf32(acc[mi][ni], af[mi], bf[ni]);
        }
        __syncthreads();
    }

    #pragma unroll
    for (int mi = 0; mi < 2; mi++) {
        #pragma unroll
        for (int half = 0; half < 2; half++) {
            const int m = bm0 + m0w + mi * 16 + g + half * 8;
            #pragma unroll
            for (int ni = 0; ni < 8; ni++) {
                const int n = bn0 + n0w + ni * 8 + 2 * t4;
                float v0 = acc[mi][ni][half * 2 + 0] + bias[n];
                float v1 = acc[mi][ni][half * 2 + 1] + bias[n + 1];
                if (EPI == 1) {
                    v0 = 0.5f * v0 * (1.0f + erff(v0 * 0.70710678118654752f));
                    v1 = 0.5f * v1 * (1.0f + erff(v1 * 0.70710678118654752f));
                }
                if (EPI == 2) {
                    float2 rv = *(const float2*)(res + (size_t)m * Mo + n);
                    v0 += rv.x; v1 += rv.y;
                }
                if (EPI == 3) {
                    if (n < 2 * Eq) {
                        const int srow = m & (Sq - 1);
                        const int c    = n & (Dq - 1);
                        float2 cc = *(const float2*)(cosT + srow * Dq + c);
                        float2 ss = *(const float2*)(sinT + srow * Dq + c);
                        float r0 = v0 * cc.x - v1 * ss.x;
                        float r1 = v1 * cc.y + v0 * ss.y;
                        v0 = r0; v1 = r1;
                    }
                }
                float2 ov; ov.x = v0; ov.y = v1;
                *(float2*)(C + (size_t)m * Mo + n) = ov;
            }
        }
    }
}

// ---------------- tensor-core flash attention, cp.async double-buffered ------
// (identical compute to Round 9 — this round instruments rather than edits)
#define K_STR 68
#define V_STR 72
#define PS_STR 68
#define KB_F (64 * K_STR)
#define VB_F (64 * V_STR)
#define ATTN_SMEM ((2 * KB_F + 2 * VB_F + 4 * 16 * PS_STR) * 4)

__global__ __launch_bounds__(128, 2)
void attn_mma(const float* __restrict__ qkv,
              const unsigned char* __restrict__ mask,
              float* __restrict__ ctx)
{
    extern __shared__ float sm[];
    float* Kbuf[2] = { sm,                sm + KB_F };
    float* Vbuf[2] = { sm + 2 * KB_F,     sm + 2 * KB_F + VB_F };
    float* Ps      = sm + 2 * KB_F + 2 * VB_F;

    const unsigned sbase = (unsigned)__cvta_generic_to_shared(sm);
    const unsigned kSm[2] = { sbase,                 sbase + KB_F * 4 };
    const unsigned vSm[2] = { sbase + 2 * KB_F * 4,  sbase + (2 * KB_F + VB_F) * 4 };

    const int tid  = threadIdx.x;
    const int warp = tid >> 5, lane = tid & 31;
    const int g    = lane >> 2, t4 = lane & 3;
    const int b = blockIdx.z, h = blockIdx.y;
    const int q0 = blockIdx.x * 64;
    float* Pw = Ps + warp * 16 * PS_STR;

    const int lrow = tid & 63;
    const int ldh  = (tid >> 6) * 32;
    const float* kgbase = qkv + (size_t)(b * Sq + lrow) * QKVC + Eq + h * Dq + ldh;

    unsigned aQ[8][4];
    {
        const float* qp = qkv + (size_t)(b * Sq + q0 + warp * 16) * QKVC + h * Dq;
        #pragma unroll
        for (int s = 0; s < 8; s++) {
            aQ[s][0] = f2tf32(qp[(size_t)g       * QKVC + 8*s + t4]);
            aQ[s][1] = f2tf32(qp[(size_t)(g + 8) * QKVC + 8*s + t4]);
            aQ[s][2] = f2tf32(qp[(size_t)g       * QKVC + 8*s + t4 + 4]);
            aQ[s][3] = f2tf32(qp[(size_t)(g + 8) * QKVC + 8*s + t4 + 4]);
        }
    }

    float m0 = -1e30f, m1 = -1e30f, l0 = 0.f, l1 = 0.f;
    float O[8][4];
    #pragma unroll
    for (int ni = 0; ni < 8; ni++)
        #pragma unroll
        for (int r = 0; r < 4; r++) O[ni][r] = 0.f;

    const float SC = 0.125f * 1.4426950408889634f;

    {
        const unsigned kd = kSm[0] + (lrow * K_STR + ldh) * 4;
        const unsigned vd = vSm[0] + (lrow * V_STR + ldh) * 4;
        #pragma unroll
        for (int u = 0; u < 8; u++) {
            cpasync16(kd + u * 16, kgbase + u * 4);
            cpasync16(vd + u * 16, kgbase + Eq + u * 4);
        }
        cpasync_commit();
    }

    for (int it = 0; it < Sq / 64; it++) {
        const int k0  = it * 64;
        const int cur = it & 1;

        cpasync_wait0();
        __syncthreads();

        if (it + 1 < Sq / 64) {
            const float* kg2 = kgbase + (size_t)(it + 1) * 64 * QKVC;
            const unsigned kd = kSm[cur ^ 1] + (lrow * K_STR + ldh) * 4;
            const unsigned vd = vSm[cur ^ 1] + (lrow * V_STR + ldh) * 4;
            #pragma unroll
            for (int u = 0; u < 8; u++) {
                cpasync16(kd + u * 16, kg2 + u * 4);
                cpasync16(vd + u * 16, kg2 + Eq + u * 4);
            }
            cpasync_commit();
        }

        const float* Ks = Kbuf[cur];
        const float* Vs = Vbuf[cur];

        float sacc[8][4];
        #pragma unroll
        for (int ni = 0; ni < 8; ni++)
            #pragma unroll
            for (int r = 0; r < 4; r++) sacc[ni][r] = 0.f;

        #pragma unroll
        for (int s = 0; s < 8; s++) {
            unsigned bk[8][2];
            #pragma unroll
            for (int ni = 0; ni < 8; ni++) {
                const int keyc = ni * 8 + g;
                bk[ni][0] = __float_as_uint(Ks[keyc * K_STR + 8*s + t4]);
                bk[ni][1] = __float_as_uint(Ks[keyc * K_STR + 8*s + t4 + 4]);
            }
            #pragma unroll
            for (int ni = 0; ni < 8; ni++)
                mma_tf32(sacc[ni], aQ[s], bk[ni]);
        }

        const unsigned char* mp = mask + b * Sq + k0;
        float mx0 = -1e30f, mx1 = -1e30f;
        #pragma unroll
        for (int ni = 0; ni < 8; ni++) {
            const bool k0m = mp[ni * 8 + 2 * t4];
            const bool k1m = mp[ni * 8 + 2 * t4 + 1];
            float v0 = k0m ? -1e30f : sacc[ni][0] * SC;
            float v1 = k1m ? -1e30f : sacc[ni][1] * SC;
            float v2 = k0m ? -1e30f : sacc[ni][2] * SC;
            float v3 = k1m ? -1e30f : sacc[ni][3] * SC;
            sacc[ni][0] = v0; sacc[ni][1] = v1;
            sacc[ni][2] = v2; sacc[ni][3] = v3;
            mx0 = fmaxf(mx0, fmaxf(v0, v1));
            mx1 = fmaxf(mx1, fmaxf(v2, v3));
        }
        mx0 = fmaxf(mx0, __shfl_xor_sync(0xffffffffu, mx0, 1));
        mx0 = fmaxf(mx0, __shfl_xor_sync(0xffffffffu, mx0, 2));
        mx1 = fmaxf(mx1, __shfl_xor_sync(0xffffffffu, mx1, 1));
        mx1 = fmaxf(mx1, __shfl_xor_sync(0xffffffffu, mx1, 2));

        const float mn0 = fmaxf(m0, mx0), mn1 = fmaxf(m1, mx1);
        float ps0 = 0.f, ps1 = 0.f;
        #pragma unroll
        for (int ni = 0; ni < 8; ni++) {
            float p0 = ex2(sacc[ni][0] - mn0);
            float p1 = ex2(sacc[ni][1] - mn0);
            float p2 = ex2(sacc[ni][2] - mn1);
            float p3 = ex2(sacc[ni][3] - mn1);
            ps0 += p0 + p1; ps1 += p2 + p3;
            float2 w0; w0.x = tf32f(p0); w0.y = tf32f(p1);
            float2 w1; w1.x = tf32f(p2); w1.y = tf32f(p3);
            *(float2*)&Pw[g       * PS_STR + ni * 8 + 2 * t4] = w0;
            *(float2*)&Pw[(g + 8) * PS_STR + ni * 8 + 2 * t4] = w1;
        }
        ps0 += __shfl_xor_sync(0xffffffffu, ps0, 1);
        ps0 += __shfl_xor_sync(0xffffffffu, ps0, 2);
        ps1 += __shfl_xor_sync(0xffffffffu, ps1, 1);
        ps1 += __shfl_xor_sync(0xffffffffu, ps1, 2);

        const float c0 = ex2(m0 - mn0), c1 = ex2(m1 - mn1);
        l0 = l0 * c0 + ps0; l1 = l1 * c1 + ps1;
        m0 = mn0; m1 = mn1;
        #pragma unroll
        for (int ni = 0; ni < 8; ni++) {
            O[ni][0] *= c0; O[ni][1] *= c0;
            O[ni][2] *= c1; O[ni][3] *= c1;
        }
        __syncwarp();

        #pragma unroll
        for (int s = 0; s < 8; s++) {
            unsigned aP[4];
            aP[0] = __float_as_uint(Pw[g       * PS_STR + 8*s + t4]);
            aP[1] = __float_as_uint(Pw[(g + 8) * PS_STR + 8*s + t4]);
            aP[2] = __float_as_uint(Pw[g       * PS_STR + 8*s + t4 + 4]);
            aP[3] = __float_as_uint(Pw[(g + 8) * PS_STR + 8*s + t4 + 4]);
            unsigned bv[8][2];
            #pragma unroll
            for (int ni = 0; ni < 8; ni++) {
                bv[ni][0] = __float_as_uint(Vs[(8*s + t4)     * V_STR + ni * 8 + g]);
                bv[ni][1] = __float_as_uint(Vs[(8*s + t4 + 4) * V_STR + ni * 8 + g]);
            }
            #pragma unroll
            for (int ni = 0; ni < 8; ni++)
                mma_tf32(O[ni], aP, bv[ni]);
        }
    }

    const float inv0 = 1.f / l0, inv1 = 1.f / l1;
    float* op0 = ctx + ((size_t)(b * Sq + q0 + warp * 16 + g)     * Hq + h) * Dq;
    float* op1 = ctx + ((size_t)(b * Sq + q0 + warp * 16 + g + 8) * Hq + h) * Dq;
    #pragma unroll
    for (int ni = 0; ni < 8; ni++) {
        float2 o0; o0.x = O[ni][0] * inv0; o0.y = O[ni][1] * inv0;
        float2 o1; o1.x = O[ni][2] * inv1; o1.y = O[ni][3] * inv1;
        *(float2*)(op0 + ni * 8 + 2 * t4) = o0;
        *(float2*)(op1 + ni * 8 + 2 * t4) = o1;
    }
}

// ---------------- LayerNorm (768) ----------------
__global__ void ln_kernel(const float* __restrict__ in,
                          const float* __restrict__ g,
                          const float* __restrict__ b,
                          float* __restrict__ out)
{
    const int row = blockIdx.x;
    const int t   = threadIdx.x;
    const float* p = in + (size_t)row * Eq;

    float v0 = p[t], v1 = p[t + 256], v2 = p[t + 512];
    float s  = v0 + v1 + v2;
    float s2 = v0*v0 + v1*v1 + v2*v2;
    #pragma unroll
    for (int o = 16; o; o >>= 1) {
        s  += __shfl_xor_sync(0xffffffffu, s,  o);
        s2 += __shfl_xor_sync(0xffffffffu, s2, o);
    }
    __shared__ float sh[2][8];
    if ((t & 31) == 0) { sh[0][t >> 5] = s; sh[1][t >> 5] = s2; }
    __syncthreads();
    float ts = 0.f, ts2 = 0.f;
    #pragma unroll
    for (int i = 0; i < 8; i++) { ts += sh[0][i]; ts2 += sh[1][i]; }

    const float mean = ts * (1.f / Eq);
    const float var  = ts2 * (1.f / Eq) - mean * mean;
    const float r    = rsqrtf(var + 1e-5f);

    float* o = out + (size_t)row * Eq;
    o[t]       = (v0 - mean) * r * g[t]       + b[t];
    o[t + 256] = (v1 - mean) * r * g[t + 256] + b[t + 256];
    o[t + 512] = (v2 - mean) * r * g[t + 512] + b[t + 512];
}

// ------------------------------- launch ---------------------------------------
extern "C" void kernel_launch(void* const* d_in, const int* in_sizes, int n_in,
                              void* d_out, int out_size)
{
    const float* x       = (const float*)d_in[0];
    const unsigned char* mask = (const unsigned char*)d_in[1];
    const float* qkv_w   = (const float*)d_in[2];
    const float* qkv_b   = (const float*)d_in[3];
    const float* proj_w  = (const float*)d_in[4];
    const float* proj_b  = (const float*)d_in[5];
    const float* ln1_g   = (const float*)d_in[6];
    const float* ln1_b   = (const float*)d_in[7];
    const float* w1      = (const float*)d_in[8];
    const float* b1      = (const float*)d_in[9];
    const float* w2      = (const float*)d_in[10];
    const float* b2      = (const float*)d_in[11];
    const float* ln2_g   = (const float*)d_in[12];
    const float* ln2_b   = (const float*)d_in[13];
    const float* rope_c  = (const float*)d_in[14];
    const float* rope_s  = (const float*)d_in[15];
    float* out = (float*)d_out;

    float *qkv, *ctx, *y1, *x1, *hb;
    cudaGetSymbolAddress((void**)&qkv, g_qkv);
    cudaGetSymbolAddress((void**)&ctx, g_ctx);
    cudaGetSymbolAddress((void**)&y1,  g_y1);
    cudaGetSymbolAddress((void**)&x1,  g_x1);
    cudaGetSymbolAddress((void**)&hb,  g_h);

    static bool attr_set = false;
    if (!attr_set) {
        cudaFuncSetAttribute(attn_mma,
                             cudaFuncAttributeMaxDynamicSharedMemorySize, ATTN_SMEM);
        attr_set = true;
    }

    // 1. QKV projection + bias + fused 2D RoPE            (launch index 0)
    gemm_tf32<3><<<dim3(QKVC/128, NTOK/128), 256>>>(x, qkv_w, qkv_b, nullptr,
                                                    rope_c, rope_s,
                                                    qkv, NTOK, Eq, QKVC);
    // padding no-ops                                      (launch indices 1-4)
    dummy_kernel<<<1, 32>>>();
    dummy_kernel<<<1, 32>>>();
    dummy_kernel<<<1, 32>>>();
    dummy_kernel<<<1, 32>>>();
    // 2. tensor-core flash attention                      (launch index 5 — PROFILED)
    attn_mma<<<dim3(Sq/64, Hq, Bq), 128, ATTN_SMEM>>>(qkv, mask, ctx);
    // 3. out-proj + bias + residual(x)
    gemm_tf32<2><<<dim3(Eq/128, NTOK/128), 256>>>(ctx, proj_w, proj_b, x,
                                                  nullptr, nullptr,
                                                  y1, NTOK, Eq, Eq);
    // 4. LN1
    ln_kernel<<<NTOK, 256>>>(y1, ln1_g, ln1_b, x1);
    // 5. FC1 + bias + gelu
    gemm_tf32<1><<<dim3(Mq/128, NTOK/128), 256>>>(x1, w1, b1, nullptr,
                                                  nullptr, nullptr,
                                                  hb, NTOK, Eq, Mq);
    // 6. FC2 + bias + residual(x1)
    gemm_tf32<2><<<dim3(Eq/128, NTOK/128), 256>>>(hb, w2, b2, x1,
                                                  nullptr, nullptr,
                                                  out, NTOK, Mq, Eq);
    // 7. LN2 in-place
    ln_kernel<<<NTOK, 256>>>(out, ln2_g, ln2_b, out);
}

// round 14
// speedup vs baseline: 1.2794x; 1.2794x over previous
#include <cuda_runtime.h>
#include <cuda_bf16.h>
#include <cstdint>
#include <math.h>

#define Bq 8
#define Sq 1024
#define Eq 768
#define Hq 12
#define Dq 64
#define Mq 3072
#define NTOK (Bq*Sq)          // 8192
#define QKVC (3*Eq)           // 2304

// ---------------- scratch ----------------
__device__ float g_qkv[NTOK*QKVC];
__device__ float g_ctx[NTOK*Eq];
__device__ float g_y1 [NTOK*Eq];
__device__ float g_x1 [NTOK*Eq];
__device__ float g_h  [NTOK*Mq];

// ---------------- tf32 helpers ----------------
__device__ __forceinline__ unsigned f2tf32(float x) {
    unsigned u;
    asm("cvt.rna.tf32.f32 %0, %1;" : "=r"(u) : "f"(x));
    return u;
}
__device__ __forceinline__ float tf32f(float x) { return __uint_as_float(f2tf32(x)); }

__device__ __forceinline__ void mma_tf32(float* d, const unsigned* a, const unsigned* b) {
    asm volatile(
        "mma.sync.aligned.m16n8k8.row.col.f32.tf32.tf32.f32 "
        "{%0,%1,%2,%3}, {%4,%5,%6,%7}, {%8,%9}, {%0,%1,%2,%3};"
        : "+f"(d[0]), "+f"(d[1]), "+f"(d[2]), "+f"(d[3])
        : "r"(a[0]), "r"(a[1]), "r"(a[2]), "r"(a[3]),
          "r"(b[0]), "r"(b[1]));
}

__device__ __forceinline__ float ex2(float x) {
    float y;
    asm("ex2.approx.ftz.f32 %0, %1;" : "=f"(y) : "f"(x));
    return y;
}

__device__ __forceinline__ void cpasync16(unsigned dst, const void* src) {
    asm volatile("cp.async.cg.shared.global [%0], [%1], 16;" :: "r"(dst), "l"(src));
}
__device__ __forceinline__ void cpasync_commit() {
    asm volatile("cp.async.commit_group;" ::: "memory");
}
__device__ __forceinline__ void cpasync_wait0() {
    asm volatile("cp.async.wait_group 0;" ::: "memory");
}

// ---------------- tf32 tensor-core GEMM: C[N,Mo] = A[N,K] @ W[Mo,K]^T -------
// EPI: 0=+bias ; 1=+bias,gelu ; 2=+bias,+res ; 3=+bias,rope(q,k cols)
template<int EPI>
__global__ __launch_bounds__(256, 1)
void gemm_tf32(const float* __restrict__ A,
               const float* __restrict__ W,
               const float* __restrict__ bias,
               const float* __restrict__ res,
               const float* __restrict__ cosT,
               const float* __restrict__ sinT,
               float* __restrict__ C,
               int N, int K, int Mo)
{
    constexpr int KS = 36;
    __shared__ float As[128 * KS];
    __shared__ float Bs[128 * KS];

    const int tid  = threadIdx.x;
    const int warp = tid >> 5, lane = tid & 31;
    const int g    = lane >> 2, t4 = lane & 3;
    const int wm   = warp >> 1, wn = warp & 1;
    const int m0w  = wm * 32,  n0w = wn * 64;
    const int bm0  = blockIdx.y * 128;
    const int bn0  = blockIdx.x * 128;

    const int arow = tid >> 1;
    const int acol = (tid & 1) * 16;

    const float* Ap = A + (size_t)(bm0 + arow) * K + acol;
    const float* Wp = W + (size_t)(bn0 + arow) * K + acol;

    float acc[2][8][4];
    #pragma unroll
    for (int mi = 0; mi < 2; mi++)
        #pragma unroll
        for (int ni = 0; ni < 8; ni++)
            #pragma unroll
            for (int r = 0; r < 4; r++) acc[mi][ni][r] = 0.f;

    float4 pa[4], pb[4];
    #pragma unroll
    for (int u = 0; u < 4; u++) {
        pa[u] = *(const float4*)(Ap + u * 4);
        pb[u] = *(const float4*)(Wp + u * 4);
    }

    const int T = K / 32;
    for (int t = 0; t < T; t++) {
        #pragma unroll
        for (int u = 0; u < 4; u++) {
            float4 ca, cb;
            ca.x = tf32f(pa[u].x); ca.y = tf32f(pa[u].y);
            ca.z = tf32f(pa[u].z); ca.w = tf32f(pa[u].w);
            cb.x = tf32f(pb[u].x); cb.y = tf32f(pb[u].y);
            cb.z = tf32f(pb[u].z); cb.w = tf32f(pb[u].w);
            *(float4*)&As[arow * KS + acol + u * 4] = ca;
            *(float4*)&Bs[arow * KS + acol + u * 4] = cb;
        }
        __syncthreads();

        if (t + 1 < T) {
            const float* Ap2 = Ap + (t + 1) * 32;
            const float* Wp2 = Wp + (t + 1) * 32;
            #pragma unroll
            for (int u = 0; u < 4; u++) {
                pa[u] = *(const float4*)(Ap2 + u * 4);
                pb[u] = *(const float4*)(Wp2 + u * 4);
            }
        }

        #pragma unroll
        for (int kk = 0; kk < 32; kk += 8) {
            unsigned af[2][4], bf[8][2];
            #pragma unroll
            for (int mi = 0; mi < 2; mi++) {
                const int mr = m0w + mi * 16;
                af[mi][0] = __float_as_uint(As[(mr + g)     * KS + kk + t4]);
                af[mi][1] = __float_as_uint(As[(mr + g + 8) * KS + kk + t4]);
                af[mi][2] = __float_as_uint(As[(mr + g)     * KS + kk + t4 + 4]);
                af[mi][3] = __float_as_uint(As[(mr + g + 8) * KS + kk + t4 + 4]);
            }
            #pragma unroll
            for (int ni = 0; ni < 8; ni++) {
                const int nr = n0w + ni * 8 + g;
                bf[ni][0] = __float_as_uint(Bs[nr * KS + kk + t4]);
                bf[ni][1] = __float_as_uint(Bs[nr * KS + kk + t4 + 4]);
            }
            #pragma unroll
            for (int mi = 0; mi < 2; mi++)
                #pragma unroll
                for (int ni = 0; ni < 8; ni++)
                    mma_tf32(acc[mi][ni], af[mi], bf[ni]);
        }
        __syncthreads();
    }

    #pragma unroll
    for (int mi = 0; mi < 2; mi++) {
        #pragma unroll
        for (int half = 0; half < 2; half++) {
            const int m = bm0 + m0w + mi * 16 + g + half * 8;
            #pragma unroll
            for (int ni = 0; ni < 8; ni++) {
                const int n = bn0 + n0w + ni * 8 + 2 * t4;
                float v0 = acc[mi][ni][half * 2 + 0] + bias[n];
                float v1 = acc[mi][ni][half * 2 + 1] + bias[n + 1];
                if (EPI == 1) {
                    v0 = 0.5f * v0 * (1.0f + erff(v0 * 0.70710678118654752f));
                    v1 = 0.5f * v1 * (1.0f + erff(v1 * 0.70710678118654752f));
                }
                if (EPI == 2) {
                    float2 rv = *(const float2*)(res + (size_t)m * Mo + n);
                    v0 += rv.x; v1 += rv.y;
                }
                if (EPI == 3) {
                    if (n < 2 * Eq) {
                        const int srow = m & (Sq - 1);
                        const int c    = n & (Dq - 1);
                        float2 cc = *(const float2*)(cosT + srow * Dq + c);
                        float2 ss = *(const float2*)(sinT + srow * Dq + c);
                        float r0 = v0 * cc.x - v1 * ss.x;
                        float r1 = v1 * cc.y + v0 * ss.y;
                        v0 = r0; v1 = r1;
                    }
                }
                float2 ov; ov.x = v0; ov.y = v1;
                *(float2*)(C + (size_t)m * Mo + n) = ov;
            }
        }
    }
}

// ---------------- tensor-core flash attention, cp.async double-buffered ------
// (byte-identical compute to Round 9; launched TWICE this round to measure its
//  cost via the timer: dur_delta vs 1848us baseline = attn duration)
#define K_STR 68
#define V_STR 72
#define PS_STR 68
#define KB_F (64 * K_STR)
#define VB_F (64 * V_STR)
#define ATTN_SMEM ((2 * KB_F + 2 * VB_F + 4 * 16 * PS_STR) * 4)

__global__ __launch_bounds__(128, 2)
void attn_mma(const float* __restrict__ qkv,
              const unsigned char* __restrict__ mask,
              float* __restrict__ ctx)
{
    extern __shared__ float sm[];
    float* Kbuf[2] = { sm,                sm + KB_F };
    float* Vbuf[2] = { sm + 2 * KB_F,     sm + 2 * KB_F + VB_F };
    float* Ps      = sm + 2 * KB_F + 2 * VB_F;

    const unsigned sbase = (unsigned)__cvta_generic_to_shared(sm);
    const unsigned kSm[2] = { sbase,                 sbase + KB_F * 4 };
    const unsigned vSm[2] = { sbase + 2 * KB_F * 4,  sbase + (2 * KB_F + VB_F) * 4 };

    const int tid  = threadIdx.x;
    const int warp = tid >> 5, lane = tid & 31;
    const int g    = lane >> 2, t4 = lane & 3;
    const int b = blockIdx.z, h = blockIdx.y;
    const int q0 = blockIdx.x * 64;
    float* Pw = Ps + warp * 16 * PS_STR;

    const int lrow = tid & 63;
    const int ldh  = (tid >> 6) * 32;
    const float* kgbase = qkv + (size_t)(b * Sq + lrow) * QKVC + Eq + h * Dq + ldh;

    unsigned aQ[8][4];
    {
        const float* qp = qkv + (size_t)(b * Sq + q0 + warp * 16) * QKVC + h * Dq;
        #pragma unroll
        for (int s = 0; s < 8; s++) {
            aQ[s][0] = f2tf32(qp[(size_t)g       * QKVC + 8*s + t4]);
            aQ[s][1] = f2tf32(qp[(size_t)(g + 8) * QKVC + 8*s + t4]);
            aQ[s][2] = f2tf32(qp[(size_t)g       * QKVC + 8*s + t4 + 4]);
            aQ[s][3] = f2tf32(qp[(size_t)(g + 8) * QKVC + 8*s + t4 + 4]);
        }
    }

    float m0 = -1e30f, m1 = -1e30f, l0 = 0.f, l1 = 0.f;
    float O[8][4];
    #pragma unroll
    for (int ni = 0; ni < 8; ni++)
        #pragma unroll
        for (int r = 0; r < 4; r++) O[ni][r] = 0.f;

    const float SC = 0.125f * 1.4426950408889634f;

    {
        const unsigned kd = kSm[0] + (lrow * K_STR + ldh) * 4;
        const unsigned vd = vSm[0] + (lrow * V_STR + ldh) * 4;
        #pragma unroll
        for (int u = 0; u < 8; u++) {
            cpasync16(kd + u * 16, kgbase + u * 4);
            cpasync16(vd + u * 16, kgbase + Eq + u * 4);
        }
        cpasync_commit();
    }

    for (int it = 0; it < Sq / 64; it++) {
        const int k0  = it * 64;
        const int cur = it & 1;

        cpasync_wait0();
        __syncthreads();

        if (it + 1 < Sq / 64) {
            const float* kg2 = kgbase + (size_t)(it + 1) * 64 * QKVC;
            const unsigned kd = kSm[cur ^ 1] + (lrow * K_STR + ldh) * 4;
            const unsigned vd = vSm[cur ^ 1] + (lrow * V_STR + ldh) * 4;
            #pragma unroll
            for (int u = 0; u < 8; u++) {
                cpasync16(kd + u * 16, kg2 + u * 4);
                cpasync16(vd + u * 16, kg2 + Eq + u * 4);
            }
            cpasync_commit();
        }

        const float* Ks = Kbuf[cur];
        const float* Vs = Vbuf[cur];

        float sacc[8][4];
        #pragma unroll
        for (int ni = 0; ni < 8; ni++)
            #pragma unroll
            for (int r = 0; r < 4; r++) sacc[ni][r] = 0.f;

        #pragma unroll
        for (int s = 0; s < 8; s++) {
            unsigned bk[8][2];
            #pragma unroll
            for (int ni = 0; ni < 8; ni++) {
                const int keyc = ni * 8 + g;
                bk[ni][0] = __float_as_uint(Ks[keyc * K_STR + 8*s + t4]);
                bk[ni][1] = __float_as_uint(Ks[keyc * K_STR + 8*s + t4 + 4]);
            }
            #pragma unroll
            for (int ni = 0; ni < 8; ni++)
                mma_tf32(sacc[ni], aQ[s], bk[ni]);
        }

        const unsigned char* mp = mask + b * Sq + k0;
        float mx0 = -1e30f, mx1 = -1e30f;
        #pragma unroll
        for (int ni = 0; ni < 8; ni++) {
            const bool k0m = mp[ni * 8 + 2 * t4];
            const bool k1m = mp[ni * 8 + 2 * t4 + 1];
            float v0 = k0m ? -1e30f : sacc[ni][0] * SC;
            float v1 = k1m ? -1e30f : sacc[ni][1] * SC;
            float v2 = k0m ? -1e30f : sacc[ni][2] * SC;
            float v3 = k1m ? -1e30f : sacc[ni][3] * SC;
            sacc[ni][0] = v0; sacc[ni][1] = v1;
            sacc[ni][2] = v2; sacc[ni][3] = v3;
            mx0 = fmaxf(mx0, fmaxf(v0, v1));
            mx1 = fmaxf(mx1, fmaxf(v2, v3));
        }
        mx0 = fmaxf(mx0, __shfl_xor_sync(0xffffffffu, mx0, 1));
        mx0 = fmaxf(mx0, __shfl_xor_sync(0xffffffffu, mx0, 2));
        mx1 = fmaxf(mx1, __shfl_xor_sync(0xffffffffu, mx1, 1));
        mx1 = fmaxf(mx1, __shfl_xor_sync(0xffffffffu, mx1, 2));

        const float mn0 = fmaxf(m0, mx0), mn1 = fmaxf(m1, mx1);
        float ps0 = 0.f, ps1 = 0.f;
        #pragma unroll
        for (int ni = 0; ni < 8; ni++) {
            float p0 = ex2(sacc[ni][0] - mn0);
            float p1 = ex2(sacc[ni][1] - mn0);
            float p2 = ex2(sacc[ni][2] - mn1);
            float p3 = ex2(sacc[ni][3] - mn1);
            ps0 += p0 + p1; ps1 += p2 + p3;
            float2 w0; w0.x = tf32f(p0); w0.y = tf32f(p1);
            float2 w1; w1.x = tf32f(p2); w1.y = tf32f(p3);
            *(float2*)&Pw[g       * PS_STR + ni * 8 + 2 * t4] = w0;
            *(float2*)&Pw[(g + 8) * PS_STR + ni * 8 + 2 * t4] = w1;
        }
        ps0 += __shfl_xor_sync(0xffffffffu, ps0, 1);
        ps0 += __shfl_xor_sync(0xffffffffu, ps0, 2);
        ps1 += __shfl_xor_sync(0xffffffffu, ps1, 1);
        ps1 += __shfl_xor_sync(0xffffffffu, ps1, 2);

        const float c0 = ex2(m0 - mn0), c1 = ex2(m1 - mn1);
        l0 = l0 * c0 + ps0; l1 = l1 * c1 + ps1;
        m0 = mn0; m1 = mn1;
        #pragma unroll
        for (int ni = 0; ni < 8; ni++) {
            O[ni][0] *= c0; O[ni][1] *= c0;
            O[ni][2] *= c1; O[ni][3] *= c1;
        }
        __syncwarp();

        #pragma unroll
        for (int s = 0; s < 8; s++) {
            unsigned aP[4];
            aP[0] = __float_as_uint(Pw[g       * PS_STR + 8*s + t4]);
            aP[1] = __float_as_uint(Pw[(g + 8) * PS_STR + 8*s + t4]);
            aP[2] = __float_as_uint(Pw[g       * PS_STR + 8*s + t4 + 4]);
            aP[3] = __float_as_uint(Pw[(g + 8) * PS_STR + 8*s + t4 + 4]);
            unsigned bv[8][2];
            #pragma unroll
            for (int ni = 0; ni < 8; ni++) {
                bv[ni][0] = __float_as_uint(Vs[(8*s + t4)     * V_STR + ni * 8 + g]);
                bv[ni][1] = __float_as_uint(Vs[(8*s + t4 + 4) * V_STR + ni * 8 + g]);
            }
            #pragma unroll
            for (int ni = 0; ni < 8; ni++)
                mma_tf32(O[ni], aP, bv[ni]);
        }
    }

    const float inv0 = 1.f / l0, inv1 = 1.f / l1;
    float* op0 = ctx + ((size_t)(b * Sq + q0 + warp * 16 + g)     * Hq + h) * Dq;
    float* op1 = ctx + ((size_t)(b * Sq + q0 + warp * 16 + g + 8) * Hq + h) * Dq;
    #pragma unroll
    for (int ni = 0; ni < 8; ni++) {
        float2 o0; o0.x = O[ni][0] * inv0; o0.y = O[ni][1] * inv0;
        float2 o1; o1.x = O[ni][2] * inv1; o1.y = O[ni][3] * inv1;
        *(float2*)(op0 + ni * 8 + 2 * t4) = o0;
        *(float2*)(op1 + ni * 8 + 2 * t4) = o1;
    }
}

// ---------------- LayerNorm (768) ----------------
__global__ void ln_kernel(const float* __restrict__ in,
                          const float* __restrict__ g,
                          const float* __restrict__ b,
                          float* __restrict__ out)
{
    const int row = blockIdx.x;
    const int t   = threadIdx.x;
    const float* p = in + (size_t)row * Eq;

    float v0 = p[t], v1 = p[t + 256], v2 = p[t + 512];
    float s  = v0 + v1 + v2;
    float s2 = v0*v0 + v1*v1 + v2*v2;
    #pragma unroll
    for (int o = 16; o; o >>= 1) {
        s  += __shfl_xor_sync(0xffffffffu, s,  o);
        s2 += __shfl_xor_sync(0xffffffffu, s2, o);
    }
    __shared__ float sh[2][8];
    if ((t & 31) == 0) { sh[0][t >> 5] = s; sh[1][t >> 5] = s2; }
    __syncthreads();
    float ts = 0.f, ts2 = 0.f;
    #pragma unroll
    for (int i = 0; i < 8; i++) { ts += sh[0][i]; ts2 += sh[1][i]; }

    const float mean = ts * (1.f / Eq);
    const float var  = ts2 * (1.f / Eq) - mean * mean;
    const float r    = rsqrtf(var + 1e-5f);

    float* o = out + (size_t)row * Eq;
    o[t]       = (v0 - mean) * r * g[t]       + b[t];
    o[t + 256] = (v1 - mean) * r * g[t + 256] + b[t + 256];
    o[t + 512] = (v2 - mean) * r * g[t + 512] + b[t + 512];
}

// ------------------------------- launch ---------------------------------------
extern "C" void kernel_launch(void* const* d_in, const int* in_sizes, int n_in,
                              void* d_out, int out_size)
{
    const float* x       = (const float*)d_in[0];
    const unsigned char* mask = (const unsigned char*)d_in[1];
    const float* qkv_w   = (const float*)d_in[2];
    const float* qkv_b   = (const float*)d_in[3];
    const float* proj_w  = (const float*)d_in[4];
    const float* proj_b  = (const float*)d_in[5];
    const float* ln1_g   = (const float*)d_in[6];
    const float* ln1_b   = (const float*)d_in[7];
    const float* w1      = (const float*)d_in[8];
    const float* b1      = (const float*)d_in[9];
    const float* w2      = (const float*)d_in[10];
    const float* b2      = (const float*)d_in[11];
    const float* ln2_g   = (const float*)d_in[12];
    const float* ln2_b   = (const float*)d_in[13];
    const float* rope_c  = (const float*)d_in[14];
    const float* rope_s  = (const float*)d_in[15];
    float* out = (float*)d_out;

    float *qkv, *ctx, *y1, *x1, *hb;
    cudaGetSymbolAddress((void**)&qkv, g_qkv);
    cudaGetSymbolAddress((void**)&ctx, g_ctx);
    cudaGetSymbolAddress((void**)&y1,  g_y1);
    cudaGetSymbolAddress((void**)&x1,  g_x1);
    cudaGetSymbolAddress((void**)&hb,  g_h);

    static bool attr_set = false;
    if (!attr_set) {
        cudaFuncSetAttribute(attn_mma,
                             cudaFuncAttributeMaxDynamicSharedMemorySize, ATTN_SMEM);
        attr_set = true;
    }

    // 1. QKV projection + bias + fused 2D RoPE
    gemm_tf32<3><<<dim3(QKVC/128, NTOK/128), 256>>>(x, qkv_w, qkv_b, nullptr,
                                                    rope_c, rope_s,
                                                    qkv, NTOK, Eq, QKVC);
    // 2. tensor-core flash attention — LAUNCHED TWICE (idempotent) to expose
    //    its true duration via the end-to-end timer. delta vs 1848us = attn cost.
    attn_mma<<<dim3(Sq/64, Hq, Bq), 128, ATTN_SMEM>>>(qkv, mask, ctx);
    attn_mma<<<dim3(Sq/64, Hq, Bq), 128, ATTN_SMEM>>>(qkv, mask, ctx);
    // 3. out-proj + bias + residual(x)
    gemm_tf32<2><<<dim3(Eq/128, NTOK/128), 256>>>(ctx, proj_w, proj_b, x,
                                                  nullptr, nullptr,
                                                  y1, NTOK, Eq, Eq);
    // 4. LN1
    ln_kernel<<<NTOK, 256>>>(y1, ln1_g, ln1_b, x1);
    // 5. FC1 + bias + gelu
    gemm_tf32<1><<<dim3(Mq/128, NTOK/128), 256>>>(x1, w1, b1, nullptr,
                                                  nullptr, nullptr,
                                                  hb, NTOK, Eq, Mq);
    // 6. FC2 + bias + residual(x1)
    gemm_tf32<2><<<dim3(Eq/128, NTOK/128), 256>>>(hb, w2, b2, x1,
                                                  nullptr, nullptr,
                                                  out, NTOK, Mq, Eq);
    // 7. LN2 in-place
    ln_kernel<<<NTOK, 256>>>(out, ln2_g, ln2_b, out);
}

// round 17
// speedup vs baseline: 1.7975x; 1.4050x over previous
#include <cuda_runtime.h>
#include <cuda_bf16.h>
#include <cstdint>
#include <math.h>

#define Bq 8
#define Sq 1024
#define Eq 768
#define Hq 12
#define Dq 64
#define Mq 3072
#define NTOK (Bq*Sq)          // 8192
#define QKVC (3*Eq)           // 2304

// ---------------- scratch ----------------
__device__ float g_qkv[NTOK*QKVC];
__device__ float g_ctx[NTOK*Eq];
__device__ float g_y1 [NTOK*Eq];
__device__ float g_x1 [NTOK*Eq];
__device__ float g_h  [NTOK*Mq];

// ---------------- helpers ----------------
__device__ __forceinline__ unsigned f2tf32(float x) {
    unsigned u;
    asm("cvt.rna.tf32.f32 %0, %1;" : "=r"(u) : "f"(x));
    return u;
}
__device__ __forceinline__ float tf32f(float x) { return __uint_as_float(f2tf32(x)); }

__device__ __forceinline__ void mma_tf32(float* d, const unsigned* a, const unsigned* b) {
    asm volatile(
        "mma.sync.aligned.m16n8k8.row.col.f32.tf32.tf32.f32 "
        "{%0,%1,%2,%3}, {%4,%5,%6,%7}, {%8,%9}, {%0,%1,%2,%3};"
        : "+f"(d[0]), "+f"(d[1]), "+f"(d[2]), "+f"(d[3])
        : "r"(a[0]), "r"(a[1]), "r"(a[2]), "r"(a[3]),
          "r"(b[0]), "r"(b[1]));
}

__device__ __forceinline__ float ex2(float x) {
    float y;
    asm("ex2.approx.ftz.f32 %0, %1;" : "=f"(y) : "f"(x));
    return y;
}

__device__ __forceinline__ void cpasync16(unsigned dst, const void* src) {
    asm volatile("cp.async.cg.shared.global [%0], [%1], 16;" :: "r"(dst), "l"(src));
}
__device__ __forceinline__ void cpasync_commit() {
    asm volatile("cp.async.commit_group;" ::: "memory");
}
__device__ __forceinline__ void cpasync_wait0() {
    asm volatile("cp.async.wait_group 0;" ::: "memory");
}
__device__ __forceinline__ void cpasync_wait1() {
    asm volatile("cp.async.wait_group 1;" ::: "memory");
}

// ---------------- tf32 GEMM, cp.async double-buffered, 2 CTAs/SM -----------
// C[N,Mo] = A[N,K] @ W[Mo,K]^T. Block 128x128, BK=32, 256 threads.
// EPI: 1=+bias,gelu ; 2=+bias,+res ; 3=+bias,rope(q,k cols)
#define G_KS 36
#define G_STAGE (2 * 128 * G_KS)              // floats per stage (A then B)
#define GEMM_SMEM (2 * G_STAGE * 4)           // 73728 bytes

template<int EPI>
__global__ __launch_bounds__(256, 2)
void gemm_tf32(const float* __restrict__ A,
               const float* __restrict__ W,
               const float* __restrict__ bias,
               const float* __restrict__ res,
               const float* __restrict__ cosT,
               const float* __restrict__ sinT,
               float* __restrict__ C,
               int N, int K, int Mo)
{
    extern __shared__ float smem[];
    const unsigned sb = (unsigned)__cvta_generic_to_shared(smem);

    const int tid  = threadIdx.x;
    const int warp = tid >> 5, lane = tid & 31;
    const int g    = lane >> 2, t4 = lane & 3;
    const int wm   = warp >> 1, wn = warp & 1;
    const int m0w  = wm * 32,  n0w = wn * 64;
    const int bm0  = blockIdx.y * 128;
    const int bn0  = blockIdx.x * 128;

    const int arow = tid >> 1;               // 0..127
    const int acol = (tid & 1) * 16;         // 0 or 16

    const float* Ap = A + (size_t)(bm0 + arow) * K + acol;
    const float* Wp = W + (size_t)(bn0 + arow) * K + acol;
    // smem byte offsets for this thread's staging slots
    const unsigned dA = sb + (arow * G_KS + acol) * 4;
    const unsigned dB = sb + (128 * G_KS + arow * G_KS + acol) * 4;

    float acc[2][8][4];
    #pragma unroll
    for (int mi = 0; mi < 2; mi++)
        #pragma unroll
        for (int ni = 0; ni < 8; ni++)
            #pragma unroll
            for (int r = 0; r < 4; r++) acc[mi][ni][r] = 0.f;

    const int T = K / 32;

    // prologue: stage tile 0 into stage 0
    {
        #pragma unroll
        for (int u = 0; u < 4; u++) {
            cpasync16(dA + u * 16, Ap + u * 4);
            cpasync16(dB + u * 16, Wp + u * 4);
        }
        cpasync_commit();
    }

    for (int t = 0; t < T; t++) {
        if (t + 1 < T) {
            const unsigned so = ((t + 1) & 1) * G_STAGE * 4;
            const float* ga = Ap + (t + 1) * 32;
            const float* gb = Wp + (t + 1) * 32;
            #pragma unroll
            for (int u = 0; u < 4; u++) {
                cpasync16(dA + so + u * 16, ga + u * 4);
                cpasync16(dB + so + u * 16, gb + u * 4);
            }
            cpasync_commit();
            cpasync_wait1();      // tile t complete, t+1 in flight
        } else {
            cpasync_wait0();
        }
        __syncthreads();

        const float* As = smem + (t & 1) * G_STAGE;
        const float* Bs = As + 128 * G_KS;

        #pragma unroll
        for (int kk = 0; kk < 32; kk += 8) {
            unsigned af[2][4], bf[8][2];
            #pragma unroll
            for (int mi = 0; mi < 2; mi++) {
                const int mr = m0w + mi * 16;
                af[mi][0] = __float_as_uint(As[(mr + g)     * G_KS + kk + t4]);
                af[mi][1] = __float_as_uint(As[(mr + g + 8) * G_KS + kk + t4]);
                af[mi][2] = __float_as_uint(As[(mr + g)     * G_KS + kk + t4 + 4]);
                af[mi][3] = __float_as_uint(As[(mr + g + 8) * G_KS + kk + t4 + 4]);
            }
            #pragma unroll
            for (int ni = 0; ni < 8; ni++) {
                const int nr = n0w + ni * 8 + g;
                bf[ni][0] = __float_as_uint(Bs[nr * G_KS + kk + t4]);
                bf[ni][1] = __float_as_uint(Bs[nr * G_KS + kk + t4 + 4]);
            }
            #pragma unroll
            for (int mi = 0; mi < 2; mi++)
                #pragma unroll
                for (int ni = 0; ni < 8; ni++)
                    mma_tf32(acc[mi][ni], af[mi], bf[ni]);
        }
        __syncthreads();   // stage (t&1) free for reuse by issue(t+2)
    }

    // epilogue
    #pragma unroll
    for (int mi = 0; mi < 2; mi++) {
        #pragma unroll
        for (int half = 0; half < 2; half++) {
            const int m = bm0 + m0w + mi * 16 + g + half * 8;
            #pragma unroll
            for (int ni = 0; ni < 8; ni++) {
                const int n = bn0 + n0w + ni * 8 + 2 * t4;
                float v0 = acc[mi][ni][half * 2 + 0] + bias[n];
                float v1 = acc[mi][ni][half * 2 + 1] + bias[n + 1];
                if (EPI == 1) {
                    v0 = 0.5f * v0 * (1.0f + erff(v0 * 0.70710678118654752f));
                    v1 = 0.5f * v1 * (1.0f + erff(v1 * 0.70710678118654752f));
                }
                if (EPI == 2) {
                    float2 rv = *(const float2*)(res + (size_t)m * Mo + n);
                    v0 += rv.x; v1 += rv.y;
                }
                if (EPI == 3) {
                    if (n < 2 * Eq) {
                        const int srow = m & (Sq - 1);
                        const int c    = n & (Dq - 1);
                        float2 cc = *(const float2*)(cosT + srow * Dq + c);
                        float2 ss = *(const float2*)(sinT + srow * Dq + c);
                        float r0 = v0 * cc.x - v1 * ss.x;
                        float r1 = v1 * cc.y + v0 * ss.y;
                        v0 = r0; v1 = r1;
                    }
                }
                float2 ov; ov.x = v0; ov.y = v1;
                *(float2*)(C + (size_t)m * Mo + n) = ov;
            }
        }
    }
}

// ---------------- tensor-core flash attention (R9, measured 394us) ----------
#define K_STR 68
#define V_STR 72
#define PS_STR 68
#define KB_F (64 * K_STR)
#define VB_F (64 * V_STR)
#define ATTN_SMEM ((2 * KB_F + 2 * VB_F + 4 * 16 * PS_STR) * 4)

__global__ __launch_bounds__(128, 2)
void attn_mma(const float* __restrict__ qkv,
              const unsigned char* __restrict__ mask,
              float* __restrict__ ctx)
{
    extern __shared__ float sm[];
    float* Kbuf[2] = { sm,                sm + KB_F };
    float* Vbuf[2] = { sm + 2 * KB_F,     sm + 2 * KB_F + VB_F };
    float* Ps      = sm + 2 * KB_F + 2 * VB_F;

    const unsigned sbase = (unsigned)__cvta_generic_to_shared(sm);
    const unsigned kSm[2] = { sbase,                 sbase + KB_F * 4 };
    const unsigned vSm[2] = { sbase + 2 * KB_F * 4,  sbase + (2 * KB_F + VB_F) * 4 };

    const int tid  = threadIdx.x;
    const int warp = tid >> 5, lane = tid & 31;
    const int g    = lane >> 2, t4 = lane & 3;
    const int b = blockIdx.z, h = blockIdx.y;
    const int q0 = blockIdx.x * 64;
    float* Pw = Ps + warp * 16 * PS_STR;

    const int lrow = tid & 63;
    const int ldh  = (tid >> 6) * 32;
    const float* kgbase = qkv + (size_t)(b * Sq + lrow) * QKVC + Eq + h * Dq + ldh;

    unsigned aQ[8][4];
    {
        const float* qp = qkv + (size_t)(b * Sq + q0 + warp * 16) * QKVC + h * Dq;
        #pragma unroll
        for (int s = 0; s < 8; s++) {
            aQ[s][0] = f2tf32(qp[(size_t)g       * QKVC + 8*s + t4]);
            aQ[s][1] = f2tf32(qp[(size_t)(g + 8) * QKVC + 8*s + t4]);
            aQ[s][2] = f2tf32(qp[(size_t)g       * QKVC + 8*s + t4 + 4]);
            aQ[s][3] = f2tf32(qp[(size_t)(g + 8) * QKVC + 8*s + t4 + 4]);
        }
    }

    float m0 = -1e30f, m1 = -1e30f, l0 = 0.f, l1 = 0.f;
    float O[8][4];
    #pragma unroll
    for (int ni = 0; ni < 8; ni++)
        #pragma unroll
        for (int r = 0; r < 4; r++) O[ni][r] = 0.f;

    const float SC = 0.125f * 1.4426950408889634f;

    {
        const unsigned kd = kSm[0] + (lrow * K_STR + ldh) * 4;
        const unsigned vd = vSm[0] + (lrow * V_STR + ldh) * 4;
        #pragma unroll
        for (int u = 0; u < 8; u++) {
            cpasync16(kd + u * 16, kgbase + u * 4);
            cpasync16(vd + u * 16, kgbase + Eq + u * 4);
        }
        cpasync_commit();
    }

    for (int it = 0; it < Sq / 64; it++) {
        const int k0  = it * 64;
        const int cur = it & 1;

        cpasync_wait0();
        __syncthreads();

        if (it + 1 < Sq / 64) {
            const float* kg2 = kgbase + (size_t)(it + 1) * 64 * QKVC;
            const unsigned kd = kSm[cur ^ 1] + (lrow * K_STR + ldh) * 4;
            const unsigned vd = vSm[cur ^ 1] + (lrow * V_STR + ldh) * 4;
            #pragma unroll
            for (int u = 0; u < 8; u++) {
                cpasync16(kd + u * 16, kg2 + u * 4);
                cpasync16(vd + u * 16, kg2 + Eq + u * 4);
            }
            cpasync_commit();
        }

        const float* Ks = Kbuf[cur];
        const float* Vs = Vbuf[cur];

        float sacc[8][4];
        #pragma unroll
        for (int ni = 0; ni < 8; ni++)
            #pragma unroll
            for (int r = 0; r < 4; r++) sacc[ni][r] = 0.f;

        #pragma unroll
        for (int s = 0; s < 8; s++) {
            unsigned bk[8][2];
            #pragma unroll
            for (int ni = 0; ni < 8; ni++) {
                const int keyc = ni * 8 + g;
                bk[ni][0] = __float_as_uint(Ks[keyc * K_STR + 8*s + t4]);
                bk[ni][1] = __float_as_uint(Ks[keyc * K_STR + 8*s + t4 + 4]);
            }
            #pragma unroll
            for (int ni = 0; ni < 8; ni++)
                mma_tf32(sacc[ni], aQ[s], bk[ni]);
        }

        const unsigned char* mp = mask + b * Sq + k0;
        float mx0 = -1e30f, mx1 = -1e30f;
        #pragma unroll
        for (int ni = 0; ni < 8; ni++) {
            const bool k0m = mp[ni * 8 + 2 * t4];
            const bool k1m = mp[ni * 8 + 2 * t4 + 1];
            float v0 = k0m ? -1e30f : sacc[ni][0] * SC;
            float v1 = k1m ? -1e30f : sacc[ni][1] * SC;
            float v2 = k0m ? -1e30f : sacc[ni][2] * SC;
            float v3 = k1m ? -1e30f : sacc[ni][3] * SC;
            sacc[ni][0] = v0; sacc[ni][1] = v1;
            sacc[ni][2] = v2; sacc[ni][3] = v3;
            mx0 = fmaxf(mx0, fmaxf(v0, v1));
            mx1 = fmaxf(mx1, fmaxf(v2, v3));
        }
        mx0 = fmaxf(mx0, __shfl_xor_sync(0xffffffffu, mx0, 1));
        mx0 = fmaxf(mx0, __shfl_xor_sync(0xffffffffu, mx0, 2));
        mx1 = fmaxf(mx1, __shfl_xor_sync(0xffffffffu, mx1, 1));
        mx1 = fmaxf(mx1, __shfl_xor_sync(0xffffffffu, mx1, 2));

        const float mn0 = fmaxf(m0, mx0), mn1 = fmaxf(m1, mx1);
        float ps0 = 0.f, ps1 = 0.f;
        #pragma unroll
        for (int ni = 0; ni < 8; ni++) {
            float p0 = ex2(sacc[ni][0] - mn0);
            float p1 = ex2(sacc[ni][1] - mn0);
            float p2 = ex2(sacc[ni][2] - mn1);
            float p3 = ex2(sacc[ni][3] - mn1);
            ps0 += p0 + p1; ps1 += p2 + p3;
            float2 w0; w0.x = tf32f(p0); w0.y = tf32f(p1);
            float2 w1; w1.x = tf32f(p2); w1.y = tf32f(p3);
            *(float2*)&Pw[g       * PS_STR + ni * 8 + 2 * t4] = w0;
            *(float2*)&Pw[(g + 8) * PS_STR + ni * 8 + 2 * t4] = w1;
        }
        ps0 += __shfl_xor_sync(0xffffffffu, ps0, 1);
        ps0 += __shfl_xor_sync(0xffffffffu, ps0, 2);
        ps1 += __shfl_xor_sync(0xffffffffu, ps1, 1);
        ps1 += __shfl_xor_sync(0xffffffffu, ps1, 2);

        const float c0 = ex2(m0 - mn0), c1 = ex2(m1 - mn1);
        l0 = l0 * c0 + ps0; l1 = l1 * c1 + ps1;
        m0 = mn0; m1 = mn1;
        #pragma unroll
        for (int ni = 0; ni < 8; ni++) {
            O[ni][0] *= c0; O[ni][1] *= c0;
            O[ni][2] *= c1; O[ni][3] *= c1;
        }
        __syncwarp();

        #pragma unroll
        for (int s = 0; s < 8; s++) {
            unsigned aP[4];
            aP[0] = __float_as_uint(Pw[g       * PS_STR + 8*s + t4]);
            aP[1] = __float_as_uint(Pw[(g + 8) * PS_STR + 8*s + t4]);
            aP[2] = __float_as_uint(Pw[g       * PS_STR + 8*s + t4 + 4]);
            aP[3] = __float_as_uint(Pw[(g + 8) * PS_STR + 8*s + t4 + 4]);
            unsigned bv[8][2];
            #pragma unroll
            for (int ni = 0; ni < 8; ni++) {
                bv[ni][0] = __float_as_uint(Vs[(8*s + t4)     * V_STR + ni * 8 + g]);
                bv[ni][1] = __float_as_uint(Vs[(8*s + t4 + 4) * V_STR + ni * 8 + g]);
            }
            #pragma unroll
            for (int ni = 0; ni < 8; ni++)
                mma_tf32(O[ni], aP, bv[ni]);
        }
    }

    const float inv0 = 1.f / l0, inv1 = 1.f / l1;
    float* op0 = ctx + ((size_t)(b * Sq + q0 + warp * 16 + g)     * Hq + h) * Dq;
    float* op1 = ctx + ((size_t)(b * Sq + q0 + warp * 16 + g + 8) * Hq + h) * Dq;
    #pragma unroll
    for (int ni = 0; ni < 8; ni++) {
        float2 o0; o0.x = O[ni][0] * inv0; o0.y = O[ni][1] * inv0;
        float2 o1; o1.x = O[ni][2] * inv1; o1.y = O[ni][3] * inv1;
        *(float2*)(op0 + ni * 8 + 2 * t4) = o0;
        *(float2*)(op1 + ni * 8 + 2 * t4) = o1;
    }
}

// ---------------- LayerNorm (768) ----------------
__global__ void ln_kernel(const float* __restrict__ in,
                          const float* __restrict__ g,
                          const float* __restrict__ b,
                          float* __restrict__ out)
{
    const int row = blockIdx.x;
    const int t   = threadIdx.x;
    const float* p = in + (size_t)row * Eq;

    float v0 = p[t], v1 = p[t + 256], v2 = p[t + 512];
    float s  = v0 + v1 + v2;
    float s2 = v0*v0 + v1*v1 + v2*v2;
    #pragma unroll
    for (int o = 16; o; o >>= 1) {
        s  += __shfl_xor_sync(0xffffffffu, s,  o);
        s2 += __shfl_xor_sync(0xffffffffu, s2, o);
    }
    __shared__ float sh[2][8];
    if ((t & 31) == 0) { sh[0][t >> 5] = s; sh[1][t >> 5] = s2; }
    __syncthreads();
    float ts = 0.f, ts2 = 0.f;
    #pragma unroll
    for (int i = 0; i < 8; i++) { ts += sh[0][i]; ts2 += sh[1][i]; }

    const float mean = ts * (1.f / Eq);
    const float var  = ts2 * (1.f / Eq) - mean * mean;
    const float r    = rsqrtf(var + 1e-5f);

    float* o = out + (size_t)row * Eq;
    o[t]       = (v0 - mean) * r * g[t]       + b[t];
    o[t + 256] = (v1 - mean) * r * g[t + 256] + b[t + 256];
    o[t + 512] = (v2 - mean) * r * g[t + 512] + b[t + 512];
}

// ------------------------------- launch ---------------------------------------
extern "C" void kernel_launch(void* const* d_in, const int* in_sizes, int n_in,
                              void* d_out, int out_size)
{
    const float* x       = (const float*)d_in[0];
    const unsigned char* mask = (const unsigned char*)d_in[1];
    const float* qkv_w   = (const float*)d_in[2];
    const float* qkv_b   = (const float*)d_in[3];
    const float* proj_w  = (const float*)d_in[4];
    const float* proj_b  = (const float*)d_in[5];
    const float* ln1_g   = (const float*)d_in[6];
    const float* ln1_b   = (const float*)d_in[7];
    const float* w1      = (const float*)d_in[8];
    const float* b1      = (const float*)d_in[9];
    const float* w2      = (const float*)d_in[10];
    const float* b2      = (const float*)d_in[11];
    const float* ln2_g   = (const float*)d_in[12];
    const float* ln2_b   = (const float*)d_in[13];
    const float* rope_c  = (const float*)d_in[14];
    const float* rope_s  = (const float*)d_in[15];
    float* out = (float*)d_out;

    float *qkv, *ctx, *y1, *x1, *hb;
    cudaGetSymbolAddress((void**)&qkv, g_qkv);
    cudaGetSymbolAddress((void**)&ctx, g_ctx);
    cudaGetSymbolAddress((void**)&y1,  g_y1);
    cudaGetSymbolAddress((void**)&x1,  g_x1);
    cudaGetSymbolAddress((void**)&hb,  g_h);

    static bool attr_set = false;
    if (!attr_set) {
        cudaFuncSetAttribute(attn_mma,
                             cudaFuncAttributeMaxDynamicSharedMemorySize, ATTN_SMEM);
        cudaFuncSetAttribute(gemm_tf32<1>,
                             cudaFuncAttributeMaxDynamicSharedMemorySize, GEMM_SMEM);
        cudaFuncSetAttribute(gemm_tf32<2>,
                             cudaFuncAttributeMaxDynamicSharedMemorySize, GEMM_SMEM);
        cudaFuncSetAttribute(gemm_tf32<3>,
                             cudaFuncAttributeMaxDynamicSharedMemorySize, GEMM_SMEM);
        attr_set = true;
    }

    // 1. QKV projection + bias + fused 2D RoPE
    gemm_tf32<3><<<dim3(QKVC/128, NTOK/128), 256, GEMM_SMEM>>>(
        x, qkv_w, qkv_b, nullptr, rope_c, rope_s, qkv, NTOK, Eq, QKVC);
    // 2. tensor-core flash attention
    attn_mma<<<dim3(Sq/64, Hq, Bq), 128, ATTN_SMEM>>>(qkv, mask, ctx);
    // 3. out-proj + bias + residual(x)
    gemm_tf32<2><<<dim3(Eq/128, NTOK/128), 256, GEMM_SMEM>>>(
        ctx, proj_w, proj_b, x, nullptr, nullptr, y1, NTOK, Eq, Eq);
    // 4. LN1
    ln_kernel<<<NTOK, 256>>>(y1, ln1_g, ln1_b, x1);
    // 5. FC1 + bias + gelu
    gemm_tf32<1><<<dim3(Mq/128, NTOK/128), 256, GEMM_SMEM>>>(
        x1, w1, b1, nullptr, nullptr, nullptr, hb, NTOK, Eq, Mq);
    // 6. FC2 + bias + residual(x1)
    gemm_tf32<2><<<dim3(Eq/128, NTOK/128), 256, GEMM_SMEM>>>(
        hb, w2, b2, x1, nullptr, nullptr, out, NTOK, Mq, Eq);
    // 7. LN2 in-place
    ln_kernel<<<NTOK, 256>>>(out, ln2_g, ln2_b, out);
}